// round 4
// baseline (speedup 1.0000x reference)
#include <cuda_runtime.h>

#define B_      1024
#define T_      8192
#define NW_     2048
#define NTH     512
#define NSTAGE  4
#define NCHUNK  2048          // chunks of 4 elems per row

__device__ float4       g_part[B_];
__device__ unsigned int g_count = 0;

__device__ __forceinline__ float wsumf(float v) {
#pragma unroll
    for (int o = 16; o > 0; o >>= 1) v += __shfl_down_sync(0xffffffffu, v, o);
    return v;
}
__device__ __forceinline__ double wsumd(double v) {
#pragma unroll
    for (int o = 16; o > 0; o >>= 1) v += __shfl_down_sync(0xffffffffu, v, o);
    return v;
}

__global__ void __launch_bounds__(NTH, 3) duration_loss_fused(
    const float* __restrict__ dur_pred,
    const float* __restrict__ dur_gt,
    const int*   __restrict__ ph2word,
    const int*   __restrict__ txt_tokens,
    float* __restrict__ out)
{
    __shared__ float2 s_tab[151];
    __shared__ float  s_wp[NW_], s_wg[NW_];
    __shared__ float  s_hp[NCHUNK], s_hg[NCHUNK];
    __shared__ int    s_hm[NCHUNK];
    __shared__ float  s_red[5][NTH / 32];
    __shared__ double s_dred[4][NTH / 32];
    __shared__ int    s_islast;

    const int tid  = threadIdx.x;
    const int lane = tid & 31;
    const int wid  = tid >> 5;
    const int b    = blockIdx.x;

    // token rule table: {expected_or_inf, is_ratio}
    for (int i = tid; i < 151; i += NTH) {
        float ex = 1e30f, rt = 0.0f;
        if (i == 94 || i == 100 || i == 92) ex = 2.0f;
        else if (i == 122)                  ex = 3.0f;
        else if (i == 43 || i == 27)        ex = 5.0f;
        if (i == 44 || i == 28 || i == 29 || i == 27 || i == 121 || i == 43) rt = 1.0f;
        s_tab[i] = make_float2(ex, rt);
    }
    for (int i = tid; i < NW_; i += NTH) { s_wp[i] = 0.0f; s_wg[i] = 0.0f; }
    __syncthreads();

    const float* dpr = dur_pred   + (size_t)b * T_;
    const float* gtr = dur_gt     + (size_t)b * T_;
    const int*   wr  = ph2word    + (size_t)b * T_;
    const int*   tkr = txt_tokens + (size_t)b * T_;

    float accR = 0.0f, accP = 0.0f, sp = 0.0f, sg = 0.0f;
    int   defw[NSTAGE];
    float defp[NSTAGE], defg[NSTAGE];
#pragma unroll 1
    for (int s = 0; s < NSTAGE; ++s) { defw[s] = -1; defp[s] = 0.0f; defg[s] = 0.0f; }

#pragma unroll 1
    for (int s = 0; s < NSTAGE; ++s) {
        const int j0 = s * (NTH * 4) + tid * 4;

        const float4 dp4 = *reinterpret_cast<const float4*>(dpr + j0);
        const float4 gt4 = *reinterpret_cast<const float4*>(gtr + j0);
        const int4   tk4 = *reinterpret_cast<const int4*>(tkr + j0);
        const int4   w4  = *reinterpret_cast<const int4*>(wr  + j0);

        // neighbor values: shuffle for lanes 0..30, global for warp-edge lanes
        float dpn0 = __shfl_down_sync(0xffffffffu, dp4.x, 1);
        float dpn1 = __shfl_down_sync(0xffffffffu, dp4.y, 1);
        int   tkn  = __shfl_down_sync(0xffffffffu, tk4.x, 1);
        int   wn   = __shfl_down_sync(0xffffffffu, w4.x,  1);
        int   wprev = __shfl_up_sync(0xffffffffu, w4.w, 1);
        if (lane == 31) {
            if (j0 + 4 < T_) {
                dpn0 = dpr[j0 + 4]; dpn1 = dpr[j0 + 5];
                tkn  = tkr[j0 + 4]; wn   = wr[j0 + 4];
            } else {
                dpn0 = 1e30f; dpn1 = 1e30f; tkn = 150; wn = -1;
            }
        }
        if (lane == 0) wprev = (j0 > 0) ? wr[j0 - 1] : -1;

        float dpv[6] = { dp4.x, dp4.y, dp4.z, dp4.w, dpn0, dpn1 };
        float gtv[4] = { gt4.x, gt4.y, gt4.z, gt4.w };
        int   tkv[5] = { tk4.x, tk4.y, tk4.z, tk4.w, tkn };
        int   wv[5]  = { w4.x,  w4.y,  w4.z,  w4.w,  wn  };

        // gap terms, computed once per element (elem 4 = neighbor's elem 0)
        float g[5], sa[4];
#pragma unroll
        for (int k = 0; k < 5; ++k) {
            const float2 tb = s_tab[tkv[k]];
            const float g1 = fmaxf(dpv[k] - tb.x, 0.0f);
            const float g2 = fmaxf(dpv[k] - dpv[k + 1] * (1.0f / 3.0f), 0.0f) * tb.y;
            g[k] = g1 + g2;
            if (k < 4) sa[k] = (g2 > 0.0f) ? g2 : g1;
        }

#pragma unroll
        for (int k = 0; k < 4; ++k) {
            const float rules = dpv[k] - sa[k] + g[k + 1];
            const float la = __log2f(dpv[k] + 1.0f);
            const float lr = __log2f(rules  + 1.0f);
            const float lg = __log2f(gtv[k] + 1.0f);
            const float dr = la - lr; accR = fmaf(dr, dr, accR);
            const float dq = la - lg; accP = fmaf(dq, dq, accP);
            sp += fmaxf(dpv[k], 0.0f);
            sg += gtv[k];
        }

        // ---- word-segment bookkeeping ----
        const int c = s * NTH + tid;
        float cp[4];
#pragma unroll
        for (int k = 0; k < 4; ++k) cp[k] = fmaxf(dpv[k], 0.0f);

        const bool e1 = (wv[1] == wv[0]);
        const bool e2 = e1 && (wv[2] == wv[0]);
        const bool e3 = e2 && (wv[3] == wv[0]);
        float hp = cp[0] + (e1 ? cp[1] : 0.0f) + (e2 ? cp[2] : 0.0f) + (e3 ? cp[3] : 0.0f);
        float hg = gtv[0] + (e1 ? gtv[1] : 0.0f) + (e2 ? gtv[2] : 0.0f) + (e3 ? gtv[3] : 0.0f);
        s_hp[c] = hp; s_hg[c] = hg;
        s_hm[c] = wv[0] | (e3 ? (int)0x80000000 : 0);

        // runs starting inside this chunk (unique writer per word)
        bool open = false; int rw = 0; float rp = 0.0f, rg = 0.0f;
        int pw = wprev;
#pragma unroll
        for (int k = 0; k < 4; ++k) {
            if (wv[k] != pw) {
                if (open) { s_wp[rw] = rp; s_wg[rw] = rg; }
                open = true; rw = wv[k]; rp = cp[k]; rg = gtv[k];
            } else if (open) {
                rp += cp[k]; rg += gtv[k];
            }
            pw = wv[k];
        }
        if (open) {
            if (wv[4] == rw) { defw[s] = rw; defp[s] = rp; defg[s] = rg; }
            else             { s_wp[rw] = rp; s_wg[rw] = rg; }
        }
    }
    __syncthreads();

    // resolve words spanning chunk boundaries (owner walks head-run chain)
#pragma unroll 1
    for (int s = 0; s < NSTAGE; ++s) {
        if (defw[s] >= 0) {
            const int w = defw[s];
            float p = defp[s], q = defg[s];
            int ci = s * NTH + tid + 1;
            while (ci < NCHUNK) {
                const int m = s_hm[ci];
                if ((m & 0x7fffffff) != w) break;
                p += s_hp[ci]; q += s_hg[ci];
                if (m >= 0) break;   // head run not full -> word ends here
                ++ci;
            }
            s_wp[w] = p; s_wg[w] = q;
        }
    }
    __syncthreads();

    // word-level loss (empty words give 0, word 0 excluded)
    float accW = 0.0f;
#pragma unroll
    for (int r = 0; r < NW_ / NTH; ++r) {
        const int w = r * NTH + tid;
        if (w > 0) {
            const float d = __log2f(s_wp[w] + 1.0f) - __log2f(s_wg[w] + 1.0f);
            accW = fmaf(d, d, accW);
        }
    }

    // block reduction -> per-block partial
    float v[5] = { accR, accP, accW, sp, sg };
#pragma unroll
    for (int q = 0; q < 5; ++q) {
        const float r = wsumf(v[q]);
        if (lane == 0) s_red[q][wid] = r;
    }
    __syncthreads();
    if (wid == 0) {
        float t[5];
#pragma unroll
        for (int q = 0; q < 5; ++q) {
            float x = (lane < NTH / 32) ? s_red[q][lane] : 0.0f;
            t[q] = wsumf(x);
        }
        if (lane == 0) {
            const float ds = __log2f(t[3] + 1.0f) - __log2f(t[4] + 1.0f);
            g_part[b] = make_float4(t[0], t[1], t[2], ds * ds);
            __threadfence();
            const unsigned tk = atomicAdd(&g_count, 1u);
            s_islast = (tk == (unsigned)(gridDim.x - 1));
        }
    }
    __syncthreads();

    if (s_islast) {
        __threadfence();
        double a0 = 0.0, a1 = 0.0, a2 = 0.0, a3 = 0.0;
        for (int i = tid; i < B_; i += NTH) {
            const float4 p = g_part[i];
            a0 += p.x; a1 += p.y; a2 += p.z; a3 += p.w;
        }
        double dv[4] = { a0, a1, a2, a3 };
#pragma unroll
        for (int q = 0; q < 4; ++q) {
            const double r = wsumd(dv[q]);
            if (lane == 0) s_dred[q][wid] = r;
        }
        __syncthreads();
        if (wid == 0) {
            double t[4];
#pragma unroll
            for (int q = 0; q < 4; ++q) {
                double x = (lane < NTH / 32) ? s_dred[q][lane] : 0.0;
                t[q] = wsumd(x);
            }
            if (lane == 0) {
                const double LN2SQ = 0.4804530139182014;   // ln(2)^2
                const double loss = LN2SQ * ((0.3 * t[0] + 0.6 * t[1]) / 8388608.0
                                           + 0.3 * t[2] / 2096128.0
                                           + 0.1 * t[3] / 1024.0);
                out[0] = (float)loss;
                g_count = 0;   // reset for next graph replay
            }
        }
    }
}

extern "C" void kernel_launch(void* const* d_in, const int* in_sizes, int n_in,
                              void* d_out, int out_size) {
    const float* dur_pred   = (const float*)d_in[0];
    const float* dur_gt     = (const float*)d_in[1];
    const int*   ph2word    = (const int*)d_in[2];
    const int*   txt_tokens = (const int*)d_in[3];
    duration_loss_fused<<<B_, NTH>>>(dur_pred, dur_gt, ph2word, txt_tokens, (float*)d_out);
}